// round 9
// baseline (speedup 1.0000x reference)
#include <cuda_runtime.h>
#include <math.h>
#include <stdint.h>

#define NB 32
#define NS 8192
#define ND 256
#define NCHUNK 64          // blocks per batch in main pass
#define POS_PER_BLOCK 128  // rows per block
#define TILE_ROWS 16       // rows per cp.async tile
#define NTILES (POS_PER_BLOCK / TILE_ROWS)   // 8
#define NPRE 16            // k_pre reduction split
#define NFIN 8             // k_fin normalize split
#define EXP_OFF 48.0f      // fixed softmax offset (energies << 48+88)

// ---------------- scratch (no allocation allowed) ----------------
__device__ float g_Vp[NB * NPRE * ND];     // partial v[b] = Wa_w^T ht[b]
__device__ float g_c0[NB];                 // ht[b] . Wa_b
__device__ float g_PL[NB * NCHUNK];        // per-block partial sum (fixed offset)
__device__ float g_PA[NB * NCHUNK * ND];   // per-block partial weighted row-sum

// ---------------- cp.async helpers ----------------
__device__ __forceinline__ void cp16(uint32_t dst, const void* src) {
    asm volatile("cp.async.cg.shared.global [%0], [%1], 16;\n" :: "r"(dst), "l"(src));
}
__device__ __forceinline__ void cp_commit() {
    asm volatile("cp.async.commit_group;\n" ::: "memory");
}
template <int N>
__device__ __forceinline__ void cp_wait() {
    asm volatile("cp.async.wait_group %0;\n" :: "n"(N) : "memory");
}

// ---------------- K1: partial v[b], c0[b] (16-way split over d) ----------
__global__ void __launch_bounds__(256)
k_pre(const float* __restrict__ ht,
      const float* __restrict__ Wa_w,
      const float* __restrict__ Wa_b) {
    int g = blockIdx.x, b = blockIdx.y, t = threadIdx.x;
    __shared__ float sh[16];
    if (t < 16) sh[t] = ht[b * ND + g * 16 + t];
    __syncthreads();
    const float* Wp = Wa_w + (size_t)(g * 16) * ND + t;
    float acc = 0.f;
    #pragma unroll
    for (int d = 0; d < 16; d++)                      // 16 loads, all in flight
        acc = fmaf(sh[d], Wp[(size_t)d * ND], acc);
    g_Vp[(b * NPRE + g) * ND + t] = acc;

    if (g == 0) {   // c0 = ht . Wa_b
        __shared__ float red[ND];
        red[t] = ht[b * ND + t] * Wa_b[t];
        __syncthreads();
        for (int s = 128; s > 0; s >>= 1) {
            if (t < s) red[t] += red[t + s];
            __syncthreads();
        }
        if (t == 0) g_c0[b] = red[0];
    }
}

// ---------------- K2: 2-stage cp.async pipeline (R7 ordering) ------------
__global__ void __launch_bounds__(256, 4)
k_main(const float* __restrict__ hs, const int* __restrict__ slen,
       float* __restrict__ alpha) {
    __shared__ __align__(16) float sbuf[2][TILE_ROWS * ND];   // 2 x 16KB
    __shared__ float sA[8][ND];                                // 8KB
    __shared__ float sL[8];

    int chunk = blockIdx.x, b = blockIdx.y;
    int tid = threadIdx.x, w = tid >> 5, lane = tid & 31;
    int len = slen[b];
    int len_eff = (len == 0) ? NS : len;
    float off = (len == 0) ? -10000.f : EXP_OFF;

    if (chunk * POS_PER_BLOCK >= len_eff) return;

    const float* gsrc = hs + ((size_t)b * NS + chunk * POS_PER_BLOCK) * ND;
    uint32_t sb = (uint32_t)__cvta_generic_to_shared(&sbuf[0][0]);

    // stage tile 0
    {
        uint32_t dst = sb;
        const char* src = (const char*)gsrc;
        #pragma unroll
        for (int k = 0; k < 4; k++)
            cp16(dst + (tid + k * 256) * 16, src + (size_t)(tid + k * 256) * 16);
        cp_commit();
    }

    // fold the 16 v-partials (L2-hot) while tile 0 is in flight
    float c0 = g_c0[b];
    const float4* vp = (const float4*)(g_Vp + (size_t)b * NPRE * ND);
    float4 va = make_float4(0.f, 0.f, 0.f, 0.f);
    float4 vb = make_float4(0.f, 0.f, 0.f, 0.f);
    #pragma unroll 8
    for (int g = 0; g < NPRE; g++) {
        float4 pa = vp[g * 64 + lane], pb = vp[g * 64 + lane + 32];
        va.x += pa.x; va.y += pa.y; va.z += pa.z; va.w += pa.w;
        vb.x += pb.x; vb.y += pb.y; vb.z += pb.z; vb.w += pb.w;
    }

    float Lsum = 0.f;
    float4 Aa = make_float4(0.f, 0.f, 0.f, 0.f);
    float4 Ab = make_float4(0.f, 0.f, 0.f, 0.f);
    int s0 = chunk * POS_PER_BLOCK;

    #pragma unroll 1
    for (int t = 0; t < NTILES; t++) {
        if (t < NTILES - 1) {            // stage next tile into other buffer
            uint32_t dst = sb + ((t + 1) & 1) * (TILE_ROWS * ND * 4);
            const char* src = (const char*)(gsrc + (t + 1) * TILE_ROWS * ND);
            #pragma unroll
            for (int k = 0; k < 4; k++)
                cp16(dst + (tid + k * 256) * 16, src + (size_t)(tid + k * 256) * 16);
            cp_commit();
            cp_wait<1>();
        } else {
            cp_wait<0>();
        }
        __syncthreads();

        // compute: warp w handles rows 2w, 2w+1 of this tile
        const float* sp = sbuf[t & 1] + (2 * w) * ND;
        float4 r1a = ((const float4*)sp)[lane];
        float4 r1b = ((const float4*)sp)[lane + 32];
        float4 r2a = ((const float4*)sp)[64 + lane];
        float4 r2b = ((const float4*)sp)[64 + lane + 32];

        float p1 = r1a.x*va.x + r1a.y*va.y + r1a.z*va.z + r1a.w*va.w
                 + r1b.x*vb.x + r1b.y*vb.y + r1b.z*vb.z + r1b.w*vb.w;
        float p2 = r2a.x*va.x + r2a.y*va.y + r2a.z*va.z + r2a.w*va.w
                 + r2b.x*vb.x + r2b.y*vb.y + r2b.z*vb.z + r2b.w*vb.w;
        #pragma unroll
        for (int o = 16; o > 0; o >>= 1) {
            p1 += __shfl_xor_sync(0xffffffffu, p1, o);
            p2 += __shfl_xor_sync(0xffffffffu, p2, o);
        }
        int s = s0 + t * TILE_ROWS + 2 * w;
        float e1 = p1 + c0, e2 = p2 + c0;
        e1 = (e1 > 0.f) ? e1 : 0.2f * e1;            // leaky relu
        e2 = (e2 > 0.f) ? e2 : 0.2f * e2;
        if (s + 0 >= len) e1 = -10000.f;             // length mask
        if (s + 1 >= len) e2 = -10000.f;
        if (lane == 0)
            *(float2*)(alpha + (size_t)b * NS + s) = make_float2(e1, e2);

        float q1 = __expf(e1 - off);                 // fixed offset softmax
        float q2 = __expf(e2 - off);
        Lsum += q1 + q2;
        Aa.x = fmaf(q2, r2a.x, fmaf(q1, r1a.x, Aa.x));
        Aa.y = fmaf(q2, r2a.y, fmaf(q1, r1a.y, Aa.y));
        Aa.z = fmaf(q2, r2a.z, fmaf(q1, r1a.z, Aa.z));
        Aa.w = fmaf(q2, r2a.w, fmaf(q1, r1a.w, Aa.w));
        Ab.x = fmaf(q2, r2b.x, fmaf(q1, r1b.x, Ab.x));
        Ab.y = fmaf(q2, r2b.y, fmaf(q1, r1b.y, Ab.y));
        Ab.z = fmaf(q2, r2b.z, fmaf(q1, r1b.z, Ab.z));
        Ab.w = fmaf(q2, r2b.w, fmaf(q1, r1b.w, Ab.w));
        __syncthreads();
    }

    // combine 8 warps: plain sums (shared fixed offset)
    float* arow = sA[w];
    arow[lane * 4 + 0] = Aa.x; arow[lane * 4 + 1] = Aa.y;
    arow[lane * 4 + 2] = Aa.z; arow[lane * 4 + 3] = Aa.w;
    arow[128 + lane * 4 + 0] = Ab.x; arow[128 + lane * 4 + 1] = Ab.y;
    arow[128 + lane * 4 + 2] = Ab.z; arow[128 + lane * 4 + 3] = Ab.w;
    if (lane == 0) sL[w] = Lsum;
    __syncthreads();

    float acc = 0.f;
    #pragma unroll
    for (int j = 0; j < 8; j++) acc += sA[j][tid];
    int pid = b * NCHUNK + chunk;
    g_PA[pid * ND + tid] = acc;
    if (tid == 0) {
        float lb = 0.f;
        #pragma unroll
        for (int j = 0; j < 8; j++) lb += sL[j];
        g_PL[pid] = lb;
    }
}

// ---------------- K3: combine + context GEMV + alpha normalize -----------
// grid (NFIN, NB): sub-block 0 does combine+GEMV; all normalize a slice.
__global__ void __launch_bounds__(256)
k_fin(const float* __restrict__ Wc_w, const float* __restrict__ Wc_b,
      const int* __restrict__ slen, float* __restrict__ alpha,
      float* __restrict__ out_ctx) {
    int p = blockIdx.x, b = blockIdx.y;
    int t = threadIdx.x, w = t >> 5, lane = t & 31;
    int len = slen[b];
    int len_eff = (len == 0) ? NS : len;
    float off = (len == 0) ? -10000.f : EXP_OFF;
    int nval = (len_eff + POS_PER_BLOCK - 1) / POS_PER_BLOCK;

    __shared__ float sLs[NCHUNK];
    __shared__ __align__(16) float sm[ND];
    if (t < NCHUNK) sLs[t] = (t < nval) ? g_PL[b * NCHUNK + t] : 0.f;
    __syncthreads();
    float Lg = 0.f;
    #pragma unroll 8
    for (int j = 0; j < NCHUNK; j++) Lg += sLs[j];
    float Rinv = 1.f / Lg;

    if (p == 0) {
        float m = 0.f;
        #pragma unroll 8
        for (int j = 0; j < nval; j++)
            m += g_PA[(b * NCHUNK + j) * ND + t];
        sm[t] = m * Rinv;
        __syncthreads();
        const float4* m4 = (const float4*)sm;
        float4 ma = m4[lane], mb = m4[lane + 32];
        #pragma unroll
        for (int d = w; d < ND; d += 8) {
            const float4* wr = (const float4*)(Wc_w + d * ND);
            float4 wa = wr[lane], wb = wr[lane + 32];
            float pr = wa.x*ma.x + wa.y*ma.y + wa.z*ma.z + wa.w*ma.w
                     + wb.x*mb.x + wb.y*mb.y + wb.z*mb.z + wb.w*mb.w;
            #pragma unroll
            for (int o = 16; o > 0; o >>= 1)
                pr += __shfl_xor_sync(0xffffffffu, pr, o);
            if (lane == 0) out_ctx[b * ND + d] = pr + Wc_b[d];
        }
    }

    // normalize slice p: 256 float4 = 1024 floats
    float4* a4 = (float4*)(alpha + (size_t)b * NS) + p * 256;
    int pos = (p * 256 + t) * 4;
    if (len > 0 && pos >= len) {
        a4[t] = make_float4(0.f, 0.f, 0.f, 0.f);
    } else {
        float4 e = a4[t];
        float4 o;
        o.x = (len > 0 && pos + 0 >= len) ? 0.f : __expf(e.x - off) * Rinv;
        o.y = (len > 0 && pos + 1 >= len) ? 0.f : __expf(e.y - off) * Rinv;
        o.z = (len > 0 && pos + 2 >= len) ? 0.f : __expf(e.z - off) * Rinv;
        o.w = (len > 0 && pos + 3 >= len) ? 0.f : __expf(e.w - off) * Rinv;
        a4[t] = o;
    }
}

// ---------------- launch ----------------
extern "C" void kernel_launch(void* const* d_in, const int* in_sizes, int n_in,
                              void* d_out, int out_size) {
    const float* hs   = (const float*)d_in[0];  // [B,S,256]
    const float* ht   = (const float*)d_in[1];  // [B,256]
    const int*   slen = (const int*)  d_in[2];  // [B]
    const float* Wa_w = (const float*)d_in[3];  // [256,256]
    const float* Wa_b = (const float*)d_in[4];  // [256]
    const float* Wc_w = (const float*)d_in[5];  // [256,256]
    const float* Wc_b = (const float*)d_in[6];  // [256]

    float* alpha = (float*)d_out;                    // [B,S]
    float* ctx   = (float*)d_out + (size_t)NB * NS;  // [B,256]

    dim3 grid1(NPRE, NB);
    k_pre<<<grid1, 256>>>(ht, Wa_w, Wa_b);
    dim3 grid2(NCHUNK, NB);
    k_main<<<grid2, 256>>>(hs, slen, alpha);
    dim3 grid3(NFIN, NB);
    k_fin<<<grid3, 256>>>(Wc_w, Wc_b, slen, alpha, ctx);
}

// round 10
// speedup vs baseline: 1.0444x; 1.0444x over previous
#include <cuda_runtime.h>
#include <math.h>
#include <stdint.h>

#define NB 32
#define NS 8192
#define ND 256
#define NCHUNK 64          // blocks per batch in main pass
#define POS_PER_BLOCK 128  // rows per block
#define TILE_ROWS 16       // rows per cp.async tile
#define NTILES (POS_PER_BLOCK / TILE_ROWS)   // 8
#define NPRE 16            // k_pre reduction split
#define NFIN 8             // k_fin normalize split
#define EXP_OFF 48.0f      // fixed softmax offset (energies << 48+88)

// ---------------- scratch (no allocation allowed) ----------------
__device__ float g_Vp[NB * NPRE * ND];     // partial v[b] (k_pre out)
__device__ float g_V[NB * ND];             // final v[b]   (k_pre2 out)
__device__ float g_c0[NB];                 // ht[b] . Wa_b
__device__ float g_PL[NB * NCHUNK];        // per-block partial sum (fixed offset)
__device__ float g_PA[NB * NCHUNK * ND];   // per-block partial weighted row-sum

// ---------------- cp.async helpers ----------------
__device__ __forceinline__ void cp16(uint32_t dst, const void* src) {
    asm volatile("cp.async.cg.shared.global [%0], [%1], 16;\n" :: "r"(dst), "l"(src));
}
__device__ __forceinline__ void cp_commit() {
    asm volatile("cp.async.commit_group;\n" ::: "memory");
}
template <int N>
__device__ __forceinline__ void cp_wait() {
    asm volatile("cp.async.wait_group %0;\n" :: "n"(N) : "memory");
}

// ---------------- K1: partial v[b], c0[b] (16-way split over d) ----------
__global__ void __launch_bounds__(256)
k_pre(const float* __restrict__ ht,
      const float* __restrict__ Wa_w,
      const float* __restrict__ Wa_b) {
    int g = blockIdx.x, b = blockIdx.y, t = threadIdx.x;
    __shared__ float sh[16];
    if (t < 16) sh[t] = ht[b * ND + g * 16 + t];
    __syncthreads();
    const float* Wp = Wa_w + (size_t)(g * 16) * ND + t;
    float acc = 0.f;
    #pragma unroll
    for (int d = 0; d < 16; d++)                      // 16 loads, all in flight
        acc = fmaf(sh[d], Wp[(size_t)d * ND], acc);
    g_Vp[(b * NPRE + g) * ND + t] = acc;

    if (g == 0) {   // c0 = ht . Wa_b
        __shared__ float red[ND];
        red[t] = ht[b * ND + t] * Wa_b[t];
        __syncthreads();
        for (int s = 128; s > 0; s >>= 1) {
            if (t < s) red[t] += red[t + s];
            __syncthreads();
        }
        if (t == 0) g_c0[b] = red[0];
    }
}

// ---------------- K1b: fold 16 partials -> g_V (L2-hot, tiny) ------------
__global__ void __launch_bounds__(256)
k_pre2() {
    int b = blockIdx.x, t = threadIdx.x;
    const float* p = g_Vp + (size_t)b * NPRE * ND + t;
    float a0 = 0.f, a1 = 0.f, a2 = 0.f, a3 = 0.f;
    #pragma unroll
    for (int g = 0; g < NPRE; g += 4) {               // 16 loads in flight
        a0 += p[(g + 0) * ND];
        a1 += p[(g + 1) * ND];
        a2 += p[(g + 2) * ND];
        a3 += p[(g + 3) * ND];
    }
    g_V[b * ND + t] = (a0 + a1) + (a2 + a3);
}

// ---------------- K2: 2-stage cp.async pipeline (R7 ordering) ------------
__global__ void __launch_bounds__(256, 4)
k_main(const float* __restrict__ hs, const int* __restrict__ slen,
       float* __restrict__ alpha) {
    __shared__ __align__(16) float sbuf[2][TILE_ROWS * ND];   // 2 x 16KB
    __shared__ float sA[8][ND];                                // 8KB
    __shared__ float sL[8];

    int chunk = blockIdx.x, b = blockIdx.y;
    int tid = threadIdx.x, w = tid >> 5, lane = tid & 31;
    int len = slen[b];
    int len_eff = (len == 0) ? NS : len;
    float off = (len == 0) ? -10000.f : EXP_OFF;

    if (chunk * POS_PER_BLOCK >= len_eff) return;

    const float* gsrc = hs + ((size_t)b * NS + chunk * POS_PER_BLOCK) * ND;
    uint32_t sb = (uint32_t)__cvta_generic_to_shared(&sbuf[0][0]);

    // stage tile 0
    {
        uint32_t dst = sb;
        const char* src = (const char*)gsrc;
        #pragma unroll
        for (int k = 0; k < 4; k++)
            cp16(dst + (tid + k * 256) * 16, src + (size_t)(tid + k * 256) * 16);
        cp_commit();
    }

    // v fragments: 2 loads from final g_V (L2-hot)
    float c0 = g_c0[b];
    const float4* v4 = (const float4*)(g_V + b * ND);
    float4 va = v4[lane], vb = v4[lane + 32];

    float Lsum = 0.f;
    float4 Aa = make_float4(0.f, 0.f, 0.f, 0.f);
    float4 Ab = make_float4(0.f, 0.f, 0.f, 0.f);
    int s0 = chunk * POS_PER_BLOCK;

    #pragma unroll 1
    for (int t = 0; t < NTILES; t++) {
        if (t < NTILES - 1) {            // stage next tile into other buffer
            uint32_t dst = sb + ((t + 1) & 1) * (TILE_ROWS * ND * 4);
            const char* src = (const char*)(gsrc + (t + 1) * TILE_ROWS * ND);
            #pragma unroll
            for (int k = 0; k < 4; k++)
                cp16(dst + (tid + k * 256) * 16, src + (size_t)(tid + k * 256) * 16);
            cp_commit();
            cp_wait<1>();
        } else {
            cp_wait<0>();
        }
        __syncthreads();

        // compute: warp w handles rows 2w, 2w+1 of this tile
        const float* sp = sbuf[t & 1] + (2 * w) * ND;
        float4 r1a = ((const float4*)sp)[lane];
        float4 r1b = ((const float4*)sp)[lane + 32];
        float4 r2a = ((const float4*)sp)[64 + lane];
        float4 r2b = ((const float4*)sp)[64 + lane + 32];

        float p1 = r1a.x*va.x + r1a.y*va.y + r1a.z*va.z + r1a.w*va.w
                 + r1b.x*vb.x + r1b.y*vb.y + r1b.z*vb.z + r1b.w*vb.w;
        float p2 = r2a.x*va.x + r2a.y*va.y + r2a.z*va.z + r2a.w*va.w
                 + r2b.x*vb.x + r2b.y*vb.y + r2b.z*vb.z + r2b.w*vb.w;
        #pragma unroll
        for (int o = 16; o > 0; o >>= 1) {
            p1 += __shfl_xor_sync(0xffffffffu, p1, o);
            p2 += __shfl_xor_sync(0xffffffffu, p2, o);
        }
        int s = s0 + t * TILE_ROWS + 2 * w;
        float e1 = p1 + c0, e2 = p2 + c0;
        e1 = (e1 > 0.f) ? e1 : 0.2f * e1;            // leaky relu
        e2 = (e2 > 0.f) ? e2 : 0.2f * e2;
        if (s + 0 >= len) e1 = -10000.f;             // length mask
        if (s + 1 >= len) e2 = -10000.f;
        if (lane == 0)
            *(float2*)(alpha + (size_t)b * NS + s) = make_float2(e1, e2);

        float q1 = __expf(e1 - off);                 // fixed offset softmax
        float q2 = __expf(e2 - off);
        Lsum += q1 + q2;
        Aa.x = fmaf(q2, r2a.x, fmaf(q1, r1a.x, Aa.x));
        Aa.y = fmaf(q2, r2a.y, fmaf(q1, r1a.y, Aa.y));
        Aa.z = fmaf(q2, r2a.z, fmaf(q1, r1a.z, Aa.z));
        Aa.w = fmaf(q2, r2a.w, fmaf(q1, r1a.w, Aa.w));
        Ab.x = fmaf(q2, r2b.x, fmaf(q1, r1b.x, Ab.x));
        Ab.y = fmaf(q2, r2b.y, fmaf(q1, r1b.y, Ab.y));
        Ab.z = fmaf(q2, r2b.z, fmaf(q1, r1b.z, Ab.z));
        Ab.w = fmaf(q2, r2b.w, fmaf(q1, r1b.w, Ab.w));
        __syncthreads();
    }

    // combine 8 warps: plain sums (shared fixed offset)
    float* arow = sA[w];
    arow[lane * 4 + 0] = Aa.x; arow[lane * 4 + 1] = Aa.y;
    arow[lane * 4 + 2] = Aa.z; arow[lane * 4 + 3] = Aa.w;
    arow[128 + lane * 4 + 0] = Ab.x; arow[128 + lane * 4 + 1] = Ab.y;
    arow[128 + lane * 4 + 2] = Ab.z; arow[128 + lane * 4 + 3] = Ab.w;
    if (lane == 0) sL[w] = Lsum;
    __syncthreads();

    float acc = 0.f;
    #pragma unroll
    for (int j = 0; j < 8; j++) acc += sA[j][tid];
    int pid = b * NCHUNK + chunk;
    g_PA[pid * ND + tid] = acc;
    if (tid == 0) {
        float lb = 0.f;
        #pragma unroll
        for (int j = 0; j < 8; j++) lb += sL[j];
        g_PL[pid] = lb;
    }
}

// ---------------- K3: combine + context GEMV + alpha normalize -----------
// grid (NFIN, NB): sub-block 0 does combine+GEMV; all normalize a slice.
__global__ void __launch_bounds__(256)
k_fin(const float* __restrict__ Wc_w, const float* __restrict__ Wc_b,
      const int* __restrict__ slen, float* __restrict__ alpha,
      float* __restrict__ out_ctx) {
    int p = blockIdx.x, b = blockIdx.y;
    int t = threadIdx.x, w = t >> 5, lane = t & 31;
    int len = slen[b];
    int len_eff = (len == 0) ? NS : len;
    float off = (len == 0) ? -10000.f : EXP_OFF;
    int nval = (len_eff + POS_PER_BLOCK - 1) / POS_PER_BLOCK;

    __shared__ float sLs[NCHUNK];
    __shared__ __align__(16) float sm[ND];
    if (t < NCHUNK) sLs[t] = (t < nval) ? g_PL[b * NCHUNK + t] : 0.f;
    __syncthreads();
    float Lg = 0.f;
    #pragma unroll 8
    for (int j = 0; j < NCHUNK; j++) Lg += sLs[j];
    float Rinv = 1.f / Lg;

    if (p == 0) {
        float m = 0.f;
        #pragma unroll 8
        for (int j = 0; j < nval; j++)
            m += g_PA[(b * NCHUNK + j) * ND + t];
        sm[t] = m * Rinv;
        __syncthreads();
        const float4* m4 = (const float4*)sm;
        float4 ma = m4[lane], mb = m4[lane + 32];
        #pragma unroll
        for (int d = w; d < ND; d += 8) {
            const float4* wr = (const float4*)(Wc_w + d * ND);
            float4 wa = wr[lane], wb = wr[lane + 32];
            float pr = wa.x*ma.x + wa.y*ma.y + wa.z*ma.z + wa.w*ma.w
                     + wb.x*mb.x + wb.y*mb.y + wb.z*mb.z + wb.w*mb.w;
            #pragma unroll
            for (int o = 16; o > 0; o >>= 1)
                pr += __shfl_xor_sync(0xffffffffu, pr, o);
            if (lane == 0) out_ctx[b * ND + d] = pr + Wc_b[d];
        }
    }

    // normalize slice p: 256 float4 = 1024 floats
    float4* a4 = (float4*)(alpha + (size_t)b * NS) + p * 256;
    int pos = (p * 256 + t) * 4;
    if (len > 0 && pos >= len) {
        a4[t] = make_float4(0.f, 0.f, 0.f, 0.f);
    } else {
        float4 e = a4[t];
        float4 o;
        o.x = (len > 0 && pos + 0 >= len) ? 0.f : __expf(e.x - off) * Rinv;
        o.y = (len > 0 && pos + 1 >= len) ? 0.f : __expf(e.y - off) * Rinv;
        o.z = (len > 0 && pos + 2 >= len) ? 0.f : __expf(e.z - off) * Rinv;
        o.w = (len > 0 && pos + 3 >= len) ? 0.f : __expf(e.w - off) * Rinv;
        a4[t] = o;
    }
}

// ---------------- launch ----------------
extern "C" void kernel_launch(void* const* d_in, const int* in_sizes, int n_in,
                              void* d_out, int out_size) {
    const float* hs   = (const float*)d_in[0];  // [B,S,256]
    const float* ht   = (const float*)d_in[1];  // [B,256]
    const int*   slen = (const int*)  d_in[2];  // [B]
    const float* Wa_w = (const float*)d_in[3];  // [256,256]
    const float* Wa_b = (const float*)d_in[4];  // [256]
    const float* Wc_w = (const float*)d_in[5];  // [256,256]
    const float* Wc_b = (const float*)d_in[6];  // [256]

    float* alpha = (float*)d_out;                    // [B,S]
    float* ctx   = (float*)d_out + (size_t)NB * NS;  // [B,256]

    dim3 grid1(NPRE, NB);
    k_pre<<<grid1, 256>>>(ht, Wa_w, Wa_b);
    k_pre2<<<NB, 256>>>();
    dim3 grid2(NCHUNK, NB);
    k_main<<<grid2, 256>>>(hs, slen, alpha);
    dim3 grid3(NFIN, NB);
    k_fin<<<grid3, 256>>>(Wc_w, Wc_b, slen, alpha, ctx);
}

// round 11
// speedup vs baseline: 1.1950x; 1.1442x over previous
#include <cuda_runtime.h>
#include <math.h>
#include <stdint.h>

#define NB 32
#define NS 8192
#define ND 256
#define NCHUNK 64          // blocks per batch in main pass
#define POS_PER_BLOCK 128  // rows per block
#define TILE_ROWS 16       // rows per cp.async tile
#define NTILES (POS_PER_BLOCK / TILE_ROWS)   // 8
#define NPRE 16            // k_pre reduction split
#define EXP_OFF 48.0f      // fixed softmax offset (energies << 48+88)

// ---------------- scratch (no allocation allowed) ----------------
__device__ float g_Vp[NB * NPRE * ND];     // partial v[b] (k_pre out)
__device__ float g_V[NB * ND];             // final v[b]   (k_pre2 out)
__device__ float g_c0[NB];                 // ht[b] . Wa_b
__device__ float g_PL[NB * NCHUNK];        // per-block partial sum (fixed offset)
__device__ float g_PA[NB * NCHUNK * ND];   // per-block partial weighted row-sum

// ---------------- cp.async helpers ----------------
__device__ __forceinline__ void cp16(uint32_t dst, const void* src) {
    asm volatile("cp.async.cg.shared.global [%0], [%1], 16;\n" :: "r"(dst), "l"(src));
}
__device__ __forceinline__ void cp_commit() {
    asm volatile("cp.async.commit_group;\n" ::: "memory");
}
template <int N>
__device__ __forceinline__ void cp_wait() {
    asm volatile("cp.async.wait_group %0;\n" :: "n"(N) : "memory");
}

// ---------------- K1: partial v[b], c0[b] (16-way split over d) ----------
__global__ void __launch_bounds__(256)
k_pre(const float* __restrict__ ht,
      const float* __restrict__ Wa_w,
      const float* __restrict__ Wa_b) {
    int g = blockIdx.x, b = blockIdx.y, t = threadIdx.x;
    __shared__ float sh[16];
    if (t < 16) sh[t] = ht[b * ND + g * 16 + t];
    __syncthreads();
    const float* Wp = Wa_w + (size_t)(g * 16) * ND + t;
    float acc = 0.f;
    #pragma unroll
    for (int d = 0; d < 16; d++)                      // 16 loads, all in flight
        acc = fmaf(sh[d], Wp[(size_t)d * ND], acc);
    g_Vp[(b * NPRE + g) * ND + t] = acc;

    if (g == 0) {   // c0 = ht . Wa_b
        __shared__ float red[ND];
        red[t] = ht[b * ND + t] * Wa_b[t];
        __syncthreads();
        for (int s = 128; s > 0; s >>= 1) {
            if (t < s) red[t] += red[t + s];
            __syncthreads();
        }
        if (t == 0) g_c0[b] = red[0];
    }
}

// ---------------- K1b: fold 16 partials -> g_V (L2-hot, tiny) ------------
__global__ void __launch_bounds__(256)
k_pre2() {
    int b = blockIdx.x, t = threadIdx.x;
    const float* p = g_Vp + (size_t)b * NPRE * ND + t;
    float a0 = 0.f, a1 = 0.f, a2 = 0.f, a3 = 0.f;
    #pragma unroll
    for (int g = 0; g < NPRE; g += 4) {               // 16 loads in flight
        a0 += p[(g + 0) * ND];
        a1 += p[(g + 1) * ND];
        a2 += p[(g + 2) * ND];
        a3 += p[(g + 3) * ND];
    }
    g_V[b * ND + t] = (a0 + a1) + (a2 + a3);
}

// ---------------- K2: 2-stage cp.async pipeline (R10 exact) --------------
__global__ void __launch_bounds__(256, 4)
k_main(const float* __restrict__ hs, const int* __restrict__ slen,
       float* __restrict__ alpha) {
    __shared__ __align__(16) float sbuf[2][TILE_ROWS * ND];   // 2 x 16KB
    __shared__ float sA[8][ND];                                // 8KB
    __shared__ float sL[8];

    int chunk = blockIdx.x, b = blockIdx.y;
    int tid = threadIdx.x, w = tid >> 5, lane = tid & 31;
    int len = slen[b];
    int len_eff = (len == 0) ? NS : len;
    float off = (len == 0) ? -10000.f : EXP_OFF;

    if (chunk * POS_PER_BLOCK >= len_eff) return;

    const float* gsrc = hs + ((size_t)b * NS + chunk * POS_PER_BLOCK) * ND;
    uint32_t sb = (uint32_t)__cvta_generic_to_shared(&sbuf[0][0]);

    // stage tile 0
    {
        uint32_t dst = sb;
        const char* src = (const char*)gsrc;
        #pragma unroll
        for (int k = 0; k < 4; k++)
            cp16(dst + (tid + k * 256) * 16, src + (size_t)(tid + k * 256) * 16);
        cp_commit();
    }

    // v fragments: 2 loads from final g_V (L2-hot)
    float c0 = g_c0[b];
    const float4* v4 = (const float4*)(g_V + b * ND);
    float4 va = v4[lane], vb = v4[lane + 32];

    float Lsum = 0.f;
    float4 Aa = make_float4(0.f, 0.f, 0.f, 0.f);
    float4 Ab = make_float4(0.f, 0.f, 0.f, 0.f);
    int s0 = chunk * POS_PER_BLOCK;

    #pragma unroll 1
    for (int t = 0; t < NTILES; t++) {
        if (t < NTILES - 1) {            // stage next tile into other buffer
            uint32_t dst = sb + ((t + 1) & 1) * (TILE_ROWS * ND * 4);
            const char* src = (const char*)(gsrc + (t + 1) * TILE_ROWS * ND);
            #pragma unroll
            for (int k = 0; k < 4; k++)
                cp16(dst + (tid + k * 256) * 16, src + (size_t)(tid + k * 256) * 16);
            cp_commit();
            cp_wait<1>();
        } else {
            cp_wait<0>();
        }
        __syncthreads();

        // compute: warp w handles rows 2w, 2w+1 of this tile
        const float* sp = sbuf[t & 1] + (2 * w) * ND;
        float4 r1a = ((const float4*)sp)[lane];
        float4 r1b = ((const float4*)sp)[lane + 32];
        float4 r2a = ((const float4*)sp)[64 + lane];
        float4 r2b = ((const float4*)sp)[64 + lane + 32];

        float p1 = r1a.x*va.x + r1a.y*va.y + r1a.z*va.z + r1a.w*va.w
                 + r1b.x*vb.x + r1b.y*vb.y + r1b.z*vb.z + r1b.w*vb.w;
        float p2 = r2a.x*va.x + r2a.y*va.y + r2a.z*va.z + r2a.w*va.w
                 + r2b.x*vb.x + r2b.y*vb.y + r2b.z*vb.z + r2b.w*vb.w;
        #pragma unroll
        for (int o = 16; o > 0; o >>= 1) {
            p1 += __shfl_xor_sync(0xffffffffu, p1, o);
            p2 += __shfl_xor_sync(0xffffffffu, p2, o);
        }
        int s = s0 + t * TILE_ROWS + 2 * w;
        float e1 = p1 + c0, e2 = p2 + c0;
        e1 = (e1 > 0.f) ? e1 : 0.2f * e1;            // leaky relu
        e2 = (e2 > 0.f) ? e2 : 0.2f * e2;
        if (s + 0 >= len) e1 = -10000.f;             // length mask
        if (s + 1 >= len) e2 = -10000.f;
        if (lane == 0)
            *(float2*)(alpha + (size_t)b * NS + s) = make_float2(e1, e2);

        float q1 = __expf(e1 - off);                 // fixed offset softmax
        float q2 = __expf(e2 - off);
        Lsum += q1 + q2;
        Aa.x = fmaf(q2, r2a.x, fmaf(q1, r1a.x, Aa.x));
        Aa.y = fmaf(q2, r2a.y, fmaf(q1, r1a.y, Aa.y));
        Aa.z = fmaf(q2, r2a.z, fmaf(q1, r1a.z, Aa.z));
        Aa.w = fmaf(q2, r2a.w, fmaf(q1, r1a.w, Aa.w));
        Ab.x = fmaf(q2, r2b.x, fmaf(q1, r1b.x, Ab.x));
        Ab.y = fmaf(q2, r2b.y, fmaf(q1, r1b.y, Ab.y));
        Ab.z = fmaf(q2, r2b.z, fmaf(q1, r1b.z, Ab.z));
        Ab.w = fmaf(q2, r2b.w, fmaf(q1, r1b.w, Ab.w));
        __syncthreads();
    }

    // combine 8 warps: plain sums (shared fixed offset)
    float* arow = sA[w];
    arow[lane * 4 + 0] = Aa.x; arow[lane * 4 + 1] = Aa.y;
    arow[lane * 4 + 2] = Aa.z; arow[lane * 4 + 3] = Aa.w;
    arow[128 + lane * 4 + 0] = Ab.x; arow[128 + lane * 4 + 1] = Ab.y;
    arow[128 + lane * 4 + 2] = Ab.z; arow[128 + lane * 4 + 3] = Ab.w;
    if (lane == 0) sL[w] = Lsum;
    __syncthreads();

    float acc = 0.f;
    #pragma unroll
    for (int j = 0; j < 8; j++) acc += sA[j][tid];
    int pid = b * NCHUNK + chunk;
    g_PA[pid * ND + tid] = acc;
    if (tid == 0) {
        float lb = 0.f;
        #pragma unroll
        for (int j = 0; j < 8; j++) lb += sL[j];
        g_PL[pid] = lb;
    }
}

// ---------------- K3: combine + context GEMV + alpha normalize (R7) ------
__global__ void __launch_bounds__(256)
k_fin(const float* __restrict__ Wc_w, const float* __restrict__ Wc_b,
      const int* __restrict__ slen, float* __restrict__ alpha,
      float* __restrict__ out_ctx) {
    int b = blockIdx.x, t = threadIdx.x, w = t >> 5, lane = t & 31;
    int len = slen[b];
    int len_eff = (len == 0) ? NS : len;
    float off = (len == 0) ? -10000.f : EXP_OFF;
    int nval = (len_eff + POS_PER_BLOCK - 1) / POS_PER_BLOCK;

    __shared__ float sLs[NCHUNK];
    __shared__ __align__(16) float sm[ND];
    if (t < NCHUNK) sLs[t] = (t < nval) ? g_PL[b * NCHUNK + t] : 0.f;
    __syncthreads();
    float Lg = 0.f;
    #pragma unroll 8
    for (int j = 0; j < NCHUNK; j++) Lg += sLs[j];
    float m = 0.f;
    #pragma unroll 8
    for (int j = 0; j < nval; j++)
        m += g_PA[(b * NCHUNK + j) * ND + t];
    float Rinv = 1.f / Lg;
    m *= Rinv;
    sm[t] = m;
    __syncthreads();

    // context GEMV: warp per output row
    const float4* m4 = (const float4*)sm;
    float4 ma = m4[lane], mb = m4[lane + 32];
    #pragma unroll
    for (int d = w; d < ND; d += 8) {
        const float4* wr = (const float4*)(Wc_w + d * ND);
        float4 wa = wr[lane], wb = wr[lane + 32];
        float p = wa.x*ma.x + wa.y*ma.y + wa.z*ma.z + wa.w*ma.w
                + wb.x*mb.x + wb.y*mb.y + wb.z*mb.z + wb.w*mb.w;
        #pragma unroll
        for (int o = 16; o > 0; o >>= 1)
            p += __shfl_xor_sync(0xffffffffu, p, o);
        if (lane == 0) out_ctx[b * ND + d] = p + Wc_b[d];
    }

    // normalize this batch's alpha: 2048 float4, 8 per thread
    float4* a4 = (float4*)(alpha + (size_t)b * NS);
    float4 ev[8];
    #pragma unroll
    for (int k = 0; k < 8; k++) ev[k] = a4[k * 256 + t];
    #pragma unroll
    for (int k = 0; k < 8; k++) {
        int pos = (k * 256 + t) * 4;
        float4 o;
        if (len > 0 && pos >= len) {
            o = make_float4(0.f, 0.f, 0.f, 0.f);
        } else {
            o.x = (len > 0 && pos + 0 >= len) ? 0.f : __expf(ev[k].x - off) * Rinv;
            o.y = (len > 0 && pos + 1 >= len) ? 0.f : __expf(ev[k].y - off) * Rinv;
            o.z = (len > 0 && pos + 2 >= len) ? 0.f : __expf(ev[k].z - off) * Rinv;
            o.w = (len > 0 && pos + 3 >= len) ? 0.f : __expf(ev[k].w - off) * Rinv;
        }
        a4[k * 256 + t] = o;
    }
}

// ---------------- launch ----------------
extern "C" void kernel_launch(void* const* d_in, const int* in_sizes, int n_in,
                              void* d_out, int out_size) {
    const float* hs   = (const float*)d_in[0];  // [B,S,256]
    const float* ht   = (const float*)d_in[1];  // [B,256]
    const int*   slen = (const int*)  d_in[2];  // [B]
    const float* Wa_w = (const float*)d_in[3];  // [256,256]
    const float* Wa_b = (const float*)d_in[4];  // [256]
    const float* Wc_w = (const float*)d_in[5];  // [256,256]
    const float* Wc_b = (const float*)d_in[6];  // [256]

    float* alpha = (float*)d_out;                    // [B,S]
    float* ctx   = (float*)d_out + (size_t)NB * NS;  // [B,256]

    dim3 grid1(NPRE, NB);
    k_pre<<<grid1, 256>>>(ht, Wa_w, Wa_b);
    k_pre2<<<NB, 256>>>();
    dim3 grid2(NCHUNK, NB);
    k_main<<<grid2, 256>>>(hs, slen, alpha);
    k_fin<<<NB, 256>>>(Wc_w, Wc_b, slen, alpha, ctx);
}